// round 14
// baseline (speedup 1.0000x reference)
#include <cuda_runtime.h>
#include <cuda_fp16.h>
#include <cstdint>

// InterAttention (ESIM-style) on GB300 — fp16 mma.sync, cp.async 3-stage x 64K
// pipeline, ldmatrix(+.trans) fragment loads, fused r1/r2 launches.
// trans-B path lets value GEMMs read r1m/r2m directly and MLP/compare GEMMs
// read untransposed weights -> no transpose kernels at all.

#define NEG_INF_F (-1e10f)
#define SLOPE 0.01f
#define Bc 64
#define Lc 512
#define Dc 512
#define BLD (Bc*Lc*Dc)

// ---- scratch ----
__device__ __half g_rh  [2*BLD];   // r1h | r2h
__device__ __half g_hh  [2*BLD];   // hidden
__device__ __half g_rmh [2*BLD];   // r1m | r2m
__device__ __half g_oh  [2*BLD];   // o1  | o2T
__device__ __half g_ch  [2*BLD];   // c1  | c2
__device__ __half g_W1h [Dc*Dc];   // [K][N] as given
__device__ __half g_W2h [Dc*Dc];
__device__ __half g_Wc1h[2*Dc*Dc];
__device__ __half g_Wc2h[Dc*Dc];
__device__ float  g_S[BLD];

__device__ __forceinline__ void mma_f16(float* c, const uint32_t* a, const uint32_t* b) {
    asm volatile(
        "mma.sync.aligned.m16n8k16.row.col.f32.f16.f16.f32 "
        "{%0,%1,%2,%3}, {%4,%5,%6,%7}, {%8,%9}, {%0,%1,%2,%3};"
        : "+f"(c[0]), "+f"(c[1]), "+f"(c[2]), "+f"(c[3])
        : "r"(a[0]), "r"(a[1]), "r"(a[2]), "r"(a[3]), "r"(b[0]), "r"(b[1]));
}
#define LDSM_X4(r0, r1, r2, r3, addr) \
    asm volatile("ldmatrix.sync.aligned.m8n8.x4.shared.b16 {%0,%1,%2,%3}, [%4];" \
        : "=r"(r0), "=r"(r1), "=r"(r2), "=r"(r3) : "r"(addr))
#define LDSM_X4T(r0, r1, r2, r3, addr) \
    asm volatile("ldmatrix.sync.aligned.m8n8.x4.trans.shared.b16 {%0,%1,%2,%3}, [%4];" \
        : "=r"(r0), "=r"(r1), "=r"(r2), "=r"(r3) : "r"(addr))
#define CP_ASYNC16(saddr, gptr) \
    asm volatile("cp.async.cg.shared.global [%0], [%1], 16;" :: "r"(saddr), "l"(gptr) : "memory")
#define CP_COMMIT() asm volatile("cp.async.commit_group;" ::: "memory")
#define CP_WAIT1()  asm volatile("cp.async.wait_group 1;" ::: "memory")

__device__ __forceinline__ uint32_t smem_u32(const void* p){
    uint32_t a;
    asm("{ .reg .u64 t; cvta.to.shared.u64 t, %1; cvt.u32.u64 %0, t; }":"=r"(a):"l"(p));
    return a;
}

// ---------------- fp16 GEMM ----------------
// C[b][m][n] = epi( sum_k opA[b][m][k]*opB[b][n][k] ).
// A half [M][K] K-contig (concat via A2/Ksplit).
// transB=0: B half [N][K] K-contig (normal ldmatrix).
// transB=1: B half [K][N] N-contig (ldmatrix.trans) — weights / rm direct.
// bXor: per-batch B index = (b ^ bXor) (fused value GEMM half-swap).
// mode 0 plain; 1 bias+lrelu+rowmask(split); 2 score mask (f32 out).
#define BM 128
#define BN 128
#define BKH 64
#define SWH 72            // A / B-normal row stride (halves): 144B, conflict-free
#define BTW 136           // B-trans row stride (halves): 272B, conflict-free
#define STAGES 3
#define ASTG (BM*SWH)     // 9216 halves
#define BSTG (BM*SWH)     // 9216 (>= 64*136=8704)
#define GSMEM (STAGES*(ASTG+BSTG)*2)   // 110592 B

__global__ __launch_bounds__(256, 2)
void gemm_h(const __half* __restrict__ A, const __half* __restrict__ A2,
            const __half* __restrict__ B, void* __restrict__ Cv,
            int M, int N, int K, int Ksplit,
            int ldA, int ldA2, int ldB, int ldC,
            long sA, long sA2, long sB, long sC,
            const float* __restrict__ bias,
            const int* __restrict__ rowmask, const int* __restrict__ rowmask2,
            int Mhalf,
            const int* __restrict__ m1p, const int* __restrict__ m2p,
            int mode, int outHalf, int transB, int bXor)
{
    extern __shared__ __half smem[];
    __half* As = smem;                    // [STAGES][BM][SWH]
    __half* Bs = smem + STAGES*ASTG;      // [STAGES][...]

    const int b = blockIdx.z;
    const __half* Ab  = A  + (long)b * sA;
    const __half* A2b = A2 + (long)b * sA2;
    const __half* Bb  = B  + (long)(b ^ bXor) * sB;

    const int tid = threadIdx.x;
    const int mBlock = blockIdx.y * BM;
    const int nBlock = blockIdx.x * BN;

    const int warp = tid >> 5, lane = tid & 31;
    const int mw = (warp >> 2) * 64;
    const int nw = (warp & 3) * 32;
    const int gr = lane >> 2;
    const int tg = lane & 3;
    const int g  = lane >> 3;

    const uint32_t aBase = smem_u32(As);
    const uint32_t bBase = smem_u32(Bs);
    uint32_t aOff[4], bOff[2];
#pragma unroll
    for (int mt = 0; mt < 4; mt++)
        aOff[mt] = (uint32_t)(((mw + mt * 16 + (lane & 15)) * SWH + (lane >> 4) * 8) * 2);
    if (!transB) {
#pragma unroll
        for (int p = 0; p < 2; p++)
            bOff[p] = (uint32_t)(((nw + (p * 2 + (g >> 1)) * 8 + (lane & 7)) * SWH + (g & 1) * 8) * 2);
    } else {
#pragma unroll
        for (int p = 0; p < 2; p++)
            bOff[p] = (uint32_t)((((g & 1) * 8 + (lane & 7)) * BTW + nw + (p * 2 + (g >> 1)) * 8) * 2);
    }

    float acc[4][4][4];
#pragma unroll
    for (int i = 0; i < 4; i++)
#pragma unroll
        for (int j = 0; j < 4; j++)
#pragma unroll
            for (int q = 0; q < 4; q++) acc[i][j][q] = 0.0f;

    const int KT = K / BKH;

    auto issue = [&](int kt, int stg) {
        const int k0 = kt * BKH;
        const __half* Ap; int kb, ld;
        if (k0 < Ksplit) { Ap = Ab;  kb = k0;          ld = ldA;  }
        else             { Ap = A2b; kb = k0 - Ksplit; ld = ldA2; }
        const uint32_t sa = aBase + (uint32_t)(stg * ASTG * 2);
        const uint32_t sb = bBase + (uint32_t)(stg * BSTG * 2);
        const int r0 = tid >> 2;
        const int c0 = (tid & 3) * 16;
#pragma unroll
        for (int p = 0; p < 2; p++) {
            const int r = r0 + p * 64;
            const __half* gp = Ap + (long)(mBlock + r) * ld + kb + c0;
            const uint32_t s = sa + (uint32_t)((r * SWH + c0) * 2);
            CP_ASYNC16(s, gp);
            CP_ASYNC16(s + 16, gp + 8);
        }
        if (!transB) {
#pragma unroll
            for (int p = 0; p < 2; p++) {
                const int r = r0 + p * 64;
                const __half* gp = Bb + (long)(nBlock + r) * ldB + k0 + c0;
                const uint32_t s = sb + (uint32_t)((r * SWH + c0) * 2);
                CP_ASYNC16(s, gp);
                CP_ASYNC16(s + 16, gp + 8);
            }
        } else {
            const int ct = (tid & 3) * 32;
            const __half* gp = Bb + (long)(k0 + r0) * ldB + nBlock + ct;
            const uint32_t s = sb + (uint32_t)((r0 * BTW + ct) * 2);
#pragma unroll
            for (int q = 0; q < 4; q++) CP_ASYNC16(s + q * 16, gp + q * 8);
        }
    };

    issue(0, 0); CP_COMMIT();
    issue(1, 1); CP_COMMIT();

    for (int kt = 0; kt < KT; kt++) {
        CP_WAIT1();
        __syncthreads();
        if (kt + 2 < KT) issue(kt + 2, (kt + 2) % 3);
        CP_COMMIT();

        const int buf = kt % 3;
        const uint32_t aBuf = aBase + (uint32_t)(buf * ASTG * 2);
        const uint32_t bBuf = bBase + (uint32_t)(buf * BSTG * 2);
#pragma unroll
        for (int ks = 0; ks < 4; ks++) {          // four k16 slices
            const uint32_t aK = (uint32_t)(ks * 32);
            const uint32_t bK = transB ? (uint32_t)(ks * 16 * BTW * 2) : (uint32_t)(ks * 32);
            uint32_t af[4][4], bf[4][2];
#pragma unroll
            for (int mt = 0; mt < 4; mt++)
                LDSM_X4(af[mt][0], af[mt][1], af[mt][2], af[mt][3], aBuf + aOff[mt] + aK);
            if (!transB) {
#pragma unroll
                for (int p = 0; p < 2; p++)
                    LDSM_X4(bf[2*p][0], bf[2*p][1], bf[2*p+1][0], bf[2*p+1][1], bBuf + bOff[p] + bK);
            } else {
#pragma unroll
                for (int p = 0; p < 2; p++)
                    LDSM_X4T(bf[2*p][0], bf[2*p][1], bf[2*p+1][0], bf[2*p+1][1], bBuf + bOff[p] + bK);
            }
#pragma unroll
            for (int mt = 0; mt < 4; mt++)
#pragma unroll
                for (int nt = 0; nt < 4; nt++)
                    mma_f16(acc[mt][nt], af[mt], bf[nt]);
        }
    }

    // ---- epilogue ----
    float*  Cf = (float*) Cv + (long)b * sC;
    __half* Ch = (__half*)Cv + (long)b * sC;
#pragma unroll
    for (int mt = 0; mt < 4; mt++) {
        const int r0 = mBlock + mw + mt * 16 + gr;
#pragma unroll
        for (int half_ = 0; half_ < 2; half_++) {
            const int row = r0 + half_ * 8;
            float rm = 1.0f; int mi = 1;
            if (mode == 1 && rowmask) {
                const int useB = (rowmask2 != nullptr) && (row >= Mhalf);
                const int* rmp = useB ? rowmask2 : rowmask;
                const int rr = useB ? row - Mhalf : row;
                rm = rmp[rr] ? 1.0f : 0.0f;
            }
            if (mode == 2) mi = m1p[(long)b * M + row];
#pragma unroll
            for (int nt = 0; nt < 4; nt++) {
                const int c0 = nBlock + nw + nt * 8 + tg * 2;
                float v0 = acc[mt][nt][half_ * 2 + 0];
                float v1 = acc[mt][nt][half_ * 2 + 1];
                if (mode == 1) {
                    v0 += bias[c0];     v1 += bias[c0 + 1];
                    v0 = (v0 >= 0.0f) ? v0 : SLOPE * v0;
                    v1 = (v1 >= 0.0f) ? v1 : SLOPE * v1;
                    v0 *= rm; v1 *= rm;
                } else if (mode == 2) {
                    const int mj0 = m2p[(long)b * N + c0];
                    const int mj1 = m2p[(long)b * N + c0 + 1];
                    v0 += (mi && mj0) ? 0.0f : NEG_INF_F;
                    v1 += (mi && mj1) ? 0.0f : NEG_INF_F;
                }
                if (outHalf) {
                    *(__half2*)&Ch[(long)row * ldC + c0] = __floats2half2_rn(v0, v1);
                } else {
                    float2 o; o.x = v0; o.y = v1;
                    *(float2*)&Cf[(long)row * ldC + c0] = o;
                }
            }
        }
    }
}

// ---------------- f32 -> f16 elementwise ----------------
__global__ __launch_bounds__(256)
void f2h_kernel(const float* __restrict__ src, __half* __restrict__ dst, int n)
{
    int i = (blockIdx.x * 256 + threadIdx.x) * 4;
    if (i < n) {
        float4 v = *(const float4*)(src + i);
        *(__half2*)(dst + i)     = __floats2half2_rn(v.x, v.y);
        *(__half2*)(dst + i + 2) = __floats2half2_rn(v.z, v.w);
    }
}

// ---------------- Row softmax ----------------
__global__ __launch_bounds__(256)
void softmax_row_kernel(const float* __restrict__ S, __half* __restrict__ O,
                        const int* __restrict__ m1, const int* __restrict__ m2)
{
    const int b = blockIdx.y, i = blockIdx.x;
    const float* row = S + ((long)b * Lc + i) * Lc;
    __half* orow     = O + ((long)b * Lc + i) * Lc;
    const int tid = threadIdx.x;

    float v0 = row[tid], v1 = row[tid + 256];
    __shared__ float red[256];

    red[tid] = fmaxf(v0, v1);
    __syncthreads();
    for (int s = 128; s > 0; s >>= 1) {
        if (tid < s) red[tid] = fmaxf(red[tid], red[tid + s]);
        __syncthreads();
    }
    float mx = red[0];
    __syncthreads();

    float e0 = __expf(v0 - mx), e1 = __expf(v1 - mx);
    red[tid] = e0 + e1;
    __syncthreads();
    for (int s = 128; s > 0; s >>= 1) {
        if (tid < s) red[tid] += red[tid + s];
        __syncthreads();
    }
    float inv = 1.0f / red[0];

    int mi = m1[b * Lc + i];
    float f0 = (mi && m2[b * Lc + tid])       ? 1.0f : 0.0f;
    float f1 = (mi && m2[b * Lc + tid + 256]) ? 1.0f : 0.0f;
    orow[tid]       = __float2half_rn(e0 * inv * f0);
    orow[tid + 256] = __float2half_rn(e1 * inv * f1);
}

// -------- Column softmax, writes TRANSPOSED half result --------
__global__ __launch_bounds__(1024)
void softmax_col_kernel(const float* __restrict__ S, __half* __restrict__ OT,
                        const int* __restrict__ m1, const int* __restrict__ m2)
{
    const int b  = blockIdx.y;
    const int tx = threadIdx.x, ty = threadIdx.y;
    const int j  = blockIdx.x * 32 + tx;
    const float* Sb = S  + (long)b * Lc * Lc;
    __half* OTb     = OT + (long)b * Lc * Lc;

    float vals[16];
    float lmax = -1e30f;
#pragma unroll
    for (int it = 0; it < 16; it++) {
        int i = ty + it * 32;
        vals[it] = Sb[(long)i * Lc + j];
        lmax = fmaxf(lmax, vals[it]);
    }
    __shared__ float red[32][33];
    red[ty][tx] = lmax;
    __syncthreads();
    for (int s = 16; s > 0; s >>= 1) {
        if (ty < s) red[ty][tx] = fmaxf(red[ty][tx], red[ty + s][tx]);
        __syncthreads();
    }
    float mx = red[0][tx];
    __syncthreads();

    float lsum = 0.0f;
#pragma unroll
    for (int it = 0; it < 16; it++) {
        vals[it] = __expf(vals[it] - mx);
        lsum += vals[it];
    }
    red[ty][tx] = lsum;
    __syncthreads();
    for (int s = 16; s > 0; s >>= 1) {
        if (ty < s) red[ty][tx] += red[ty + s][tx];
        __syncthreads();
    }
    float inv = 1.0f / red[0][tx];
    __syncthreads();

    const int mj = m2[b * Lc + j];
    const int j0 = blockIdx.x * 32;
#pragma unroll
    for (int it = 0; it < 16; it++) {
        int i = ty + it * 32;
        float f = (mj && m1[b * Lc + i]) ? 1.0f : 0.0f;
        float v = vals[it] * inv * f;
        red[ty][tx] = v;
        __syncthreads();
        OTb[(long)(j0 + ty) * Lc + it * 32 + tx] = __float2half_rn(red[tx][ty]);
        __syncthreads();
    }
}

// ---------------- Launch ----------------
extern "C" void kernel_launch(void* const* d_in, const int* in_sizes, int n_in,
                              void* d_out, int out_size)
{
    const float* r1    = (const float*)d_in[0];
    const float* r2    = (const float*)d_in[1];
    const int*   mask1 = (const int*)  d_in[2];
    const int*   mask2 = (const int*)  d_in[3];
    const float* W1    = (const float*)d_in[4];
    const float* b1    = (const float*)d_in[5];
    const float* W2    = (const float*)d_in[6];
    const float* b2    = (const float*)d_in[7];
    const float* Wc1   = (const float*)d_in[8];
    const float* bc1   = (const float*)d_in[9];
    const float* Wc2   = (const float*)d_in[10];
    const float* bc2   = (const float*)d_in[11];
    float* out = (float*)d_out;

    __half *rh, *hh, *rmh, *oh, *ch, *W1h, *W2h, *Wc1h, *Wc2h;
    float *S;
    cudaGetSymbolAddress((void**)&rh,   g_rh);
    cudaGetSymbolAddress((void**)&hh,   g_hh);
    cudaGetSymbolAddress((void**)&rmh,  g_rmh);
    cudaGetSymbolAddress((void**)&oh,   g_oh);
    cudaGetSymbolAddress((void**)&ch,   g_ch);
    cudaGetSymbolAddress((void**)&W1h,  g_W1h);
    cudaGetSymbolAddress((void**)&W2h,  g_W2h);
    cudaGetSymbolAddress((void**)&Wc1h, g_Wc1h);
    cudaGetSymbolAddress((void**)&Wc2h, g_Wc2h);
    cudaGetSymbolAddress((void**)&S,    g_S);

    cudaFuncSetAttribute(gemm_h, cudaFuncAttributeMaxDynamicSharedMemorySize, GSMEM);

    const long LD = (long)Lc * Dc;   // 262144
    const int  M2 = 2 * Bc * Lc;     // 65536
    dim3 blk(256);
    dim3 gridFused(Dc / BN, M2 / BM, 1);        // (4, 512)
    dim3 gridVal(Dc / BN, Lc / BM, 2 * Bc);     // (4, 4, 128)

    // ---- inputs & weights -> half (no transposes needed: trans-B path) ----
    f2h_kernel<<<BLD / 4 / 256, 256>>>(r1, rh,       BLD);
    f2h_kernel<<<BLD / 4 / 256, 256>>>(r2, rh + BLD, BLD);
    f2h_kernel<<<Dc*Dc / 4 / 256, 256>>>(W1,  W1h,  Dc*Dc);
    f2h_kernel<<<Dc*Dc / 4 / 256, 256>>>(W2,  W2h,  Dc*Dc);
    f2h_kernel<<<2*Dc*Dc / 4 / 256, 256>>>(Wc1, Wc1h, 2*Dc*Dc);
    f2h_kernel<<<Dc*Dc / 4 / 256, 256>>>(Wc2, Wc2h, Dc*Dc);

    // ---- MLP layer 1 (fused r1|r2, B = W1 [K][N] trans) ----
    gemm_h<<<gridFused, blk, GSMEM>>>(rh, rh, W1h, hh,
        M2, Dc, Dc, 0, Dc, Dc, Dc, Dc, 0, 0, 0, 0,
        b1, nullptr, nullptr, 0, nullptr, nullptr, 1, 1, 1, 0);
    // ---- MLP layer 2 ----
    gemm_h<<<gridFused, blk, GSMEM>>>(hh, hh, W2h, rmh,
        M2, Dc, Dc, 0, Dc, Dc, Dc, Dc, 0, 0, 0, 0,
        b2, mask1, mask2, Bc*Lc, nullptr, nullptr, 1, 1, 1, 0);

    // ---- Scores: S (f32) = r1m @ r2m^T + mask (B = r2m [N][K], normal) ----
    gemm_h<<<dim3(Lc/BN, Lc/BM, Bc), blk, GSMEM>>>(rmh, rmh, rmh + BLD, S,
        Lc, Lc, Dc, 0, Dc, Dc, Dc, Lc, LD, LD, LD, LD,
        nullptr, nullptr, nullptr, 0, mask1, mask2, 2, 0, 0, 0);

    // ---- Softmaxes -> oh = [o1 | o2T] ----
    softmax_col_kernel<<<dim3(Lc/32, Bc), dim3(32, 32)>>>(S, oh + BLD, mask1, mask2);
    softmax_row_kernel<<<dim3(Lc, Bc), 256>>>(S, oh, mask1, mask2);

    // ---- value GEMMs fused (z=128): B = rmh[z^64] [K=L][N=D] trans ----
    gemm_h<<<gridVal, blk, GSMEM>>>(oh, oh, rmh, ch,
        Lc, Dc, Lc, 0, Lc, Lc, Dc, Dc, LD, LD, LD, LD,
        nullptr, nullptr, nullptr, 0, nullptr, nullptr, 0, 1, 1, 64);

    // ---- Compare layer 1 fused: [rm | c] @ Wc1 (K=1024, trans B) ----
    gemm_h<<<gridFused, blk, GSMEM>>>(rmh, ch, Wc1h, hh,
        M2, Dc, 2*Dc, Dc, Dc, Dc, Dc, Dc, 0, 0, 0, 0,
        bc1, nullptr, nullptr, 0, nullptr, nullptr, 1, 1, 1, 0);
    // ---- Compare layer 2 fused -> out (f32) ----
    gemm_h<<<gridFused, blk, GSMEM>>>(hh, hh, Wc2h, out,
        M2, Dc, Dc, 0, Dc, Dc, Dc, Dc, 0, 0, 0, 0,
        bc2, mask1, mask2, Bc*Lc, nullptr, nullptr, 1, 0, 1, 0);
}

// round 15
// speedup vs baseline: 1.1152x; 1.1152x over previous
#include <cuda_runtime.h>
#include <cuda_fp16.h>
#include <cstdint>

// InterAttention (ESIM-style) on GB300 — fp16 mma.sync, cp.async 4-stage (R13
// geometry: BKH=32, SWH=40), ldmatrix + ldmatrix.trans B path.
// trans-B removes all transpose kernels: weights read as-given [K][N], value
// GEMMs read rmh directly (batch-swap via z^64).

#define NEG_INF_F (-1e10f)
#define SLOPE 0.01f
#define Bc 64
#define Lc 512
#define Dc 512
#define BLD (Bc*Lc*Dc)

// ---- scratch ----
__device__ __half g_rh  [2*BLD];   // r1h | r2h
__device__ __half g_hh  [2*BLD];   // hidden
__device__ __half g_rmh [2*BLD];   // r1m | r2m
__device__ __half g_oh  [2*BLD];   // o1  | o2T
__device__ __half g_ch  [2*BLD];   // c1  | c2
__device__ __half g_W1h [Dc*Dc];   // [K][N] as given
__device__ __half g_W2h [Dc*Dc];
__device__ __half g_Wc1h[2*Dc*Dc];
__device__ __half g_Wc2h[Dc*Dc];
__device__ float  g_S[BLD];

__device__ __forceinline__ void mma_f16(float* c, const uint32_t* a, const uint32_t* b) {
    asm volatile(
        "mma.sync.aligned.m16n8k16.row.col.f32.f16.f16.f32 "
        "{%0,%1,%2,%3}, {%4,%5,%6,%7}, {%8,%9}, {%0,%1,%2,%3};"
        : "+f"(c[0]), "+f"(c[1]), "+f"(c[2]), "+f"(c[3])
        : "r"(a[0]), "r"(a[1]), "r"(a[2]), "r"(a[3]), "r"(b[0]), "r"(b[1]));
}
#define LDSM_X4(r0, r1, r2, r3, addr) \
    asm volatile("ldmatrix.sync.aligned.m8n8.x4.shared.b16 {%0,%1,%2,%3}, [%4];" \
        : "=r"(r0), "=r"(r1), "=r"(r2), "=r"(r3) : "r"(addr))
#define LDSM_X4T(r0, r1, r2, r3, addr) \
    asm volatile("ldmatrix.sync.aligned.m8n8.x4.trans.shared.b16 {%0,%1,%2,%3}, [%4];" \
        : "=r"(r0), "=r"(r1), "=r"(r2), "=r"(r3) : "r"(addr))
#define CP_ASYNC16(saddr, gptr) \
    asm volatile("cp.async.cg.shared.global [%0], [%1], 16;" :: "r"(saddr), "l"(gptr) : "memory")
#define CP_COMMIT() asm volatile("cp.async.commit_group;" ::: "memory")
#define CP_WAIT2()  asm volatile("cp.async.wait_group 2;" ::: "memory")

__device__ __forceinline__ uint32_t smem_u32(const void* p){
    uint32_t a;
    asm("{ .reg .u64 t; cvta.to.shared.u64 t, %1; cvt.u32.u64 %0, t; }":"=r"(a):"l"(p));
    return a;
}

// ---------------- fp16 GEMM ----------------
// C[b][m][n] = epi( sum_k opA[b][m][k]*opB[b][n][k] ).
// A half [M][K] K-contig (concat via A2/Ksplit).
// transB=0: B half [N][K] K-contig (normal ldmatrix).
// transB=1: B half [K][N] N-contig (ldmatrix.trans).
// bXor: per-batch B index = (b ^ bXor).
// mode 0 plain; 1 bias+lrelu+rowmask(split); 2 score mask (f32 out).
#define BM 128
#define BN 128
#define BKH 32
#define SWH 40            // A / B-normal row stride (halves): 80B
#define BTW 136           // B-trans row stride (halves): 272B (68 words ≡ 4 mod 32)
#define STAGES 4
#define ASTG (BM*SWH)     // 5120 halves per A stage
#define BSTG (BM*SWH)     // 5120 (trans usage 32*136=4352 fits)
#define GSMEM (STAGES*(ASTG+BSTG)*2)   // 81920 B

__global__ __launch_bounds__(256, 2)
void gemm_h(const __half* __restrict__ A, const __half* __restrict__ A2,
            const __half* __restrict__ B, void* __restrict__ Cv,
            int M, int N, int K, int Ksplit,
            int ldA, int ldA2, int ldB, int ldC,
            long sA, long sA2, long sB, long sC,
            const float* __restrict__ bias,
            const int* __restrict__ rowmask, const int* __restrict__ rowmask2,
            int Mhalf,
            const int* __restrict__ m1p, const int* __restrict__ m2p,
            int mode, int outHalf, int transB, int bXor)
{
    extern __shared__ __half smem[];
    __half* As = smem;                    // [STAGES][BM][SWH]
    __half* Bs = smem + STAGES*ASTG;

    const int b = blockIdx.z;
    const __half* Ab  = A  + (long)b * sA;
    const __half* A2b = A2 + (long)b * sA2;
    const __half* Bb  = B  + (long)(b ^ bXor) * sB;

    const int tid = threadIdx.x;
    const int mBlock = blockIdx.y * BM;
    const int nBlock = blockIdx.x * BN;

    const int warp = tid >> 5, lane = tid & 31;
    const int mw = (warp >> 2) * 64;
    const int nw = (warp & 3) * 32;
    const int gr = lane >> 2;
    const int tg = lane & 3;
    const int g  = lane >> 3;

    const uint32_t aBase = smem_u32(As);
    const uint32_t bBase = smem_u32(Bs);
    uint32_t aOff[4], bOff[2];
#pragma unroll
    for (int mt = 0; mt < 4; mt++)
        aOff[mt] = (uint32_t)(((mw + mt * 16 + (lane & 15)) * SWH + (lane >> 4) * 8) * 2);
    if (!transB) {
#pragma unroll
        for (int p = 0; p < 2; p++)
            bOff[p] = (uint32_t)(((nw + (p * 2 + (g >> 1)) * 8 + (lane & 7)) * SWH + (g & 1) * 8) * 2);
    } else {
#pragma unroll
        for (int p = 0; p < 2; p++)
            bOff[p] = (uint32_t)((((g & 1) * 8 + (lane & 7)) * BTW + nw + (p * 2 + (g >> 1)) * 8) * 2);
    }

    float acc[4][4][4];
#pragma unroll
    for (int i = 0; i < 4; i++)
#pragma unroll
        for (int j = 0; j < 4; j++)
#pragma unroll
            for (int q = 0; q < 4; q++) acc[i][j][q] = 0.0f;

    const int KT = K / BKH;

    auto issue = [&](int kt, int stg) {
        const int k0 = kt * BKH;
        const __half* Ap; int kb, ld;
        if (k0 < Ksplit) { Ap = Ab;  kb = k0;          ld = ldA;  }
        else             { Ap = A2b; kb = k0 - Ksplit; ld = ldA2; }
        const uint32_t sa = aBase + (uint32_t)(stg * ASTG * 2);
        const uint32_t sb = bBase + (uint32_t)(stg * BSTG * 2);
        {   // A tile: 128 rows x 32 halves; 4 threads/row, 16B each, 2 passes
            const int r0 = tid >> 2;
            const int c0 = (tid & 2) * 8;          // 0 or 16
            const int h0 = (tid & 1) * 8;          // 0 or 8
#pragma unroll
            for (int p = 0; p < 2; p++) {
                const int r = r0 + p * 64;
                CP_ASYNC16(sa + (uint32_t)((r * SWH + c0 + h0) * 2),
                           Ap + (long)(mBlock + r) * ld + kb + c0 + h0);
            }
        }
        if (!transB) {
            const int r0 = tid >> 2;
            const int c0 = (tid & 2) * 8;
            const int h0 = (tid & 1) * 8;
#pragma unroll
            for (int p = 0; p < 2; p++) {
                const int r = r0 + p * 64;
                CP_ASYNC16(sb + (uint32_t)((r * SWH + c0 + h0) * 2),
                           Bb + (long)(nBlock + r) * ldB + k0 + c0 + h0);
            }
        } else {
            // B tile trans: 32 rows (K) x 128 cols (N); 8 threads/row, 16 halves each
            const int r = tid >> 3;                // 0..31
            const int c = (tid & 7) * 16;          // 0..112
            const __half* gp = Bb + (long)(k0 + r) * ldB + nBlock + c;
            const uint32_t s = sb + (uint32_t)((r * BTW + c) * 2);
            CP_ASYNC16(s, gp);
            CP_ASYNC16(s + 16, gp + 8);
        }
    };

    // prologue: stages 0..2
#pragma unroll
    for (int s = 0; s < STAGES - 1; s++) { issue(s, s); CP_COMMIT(); }

    for (int kt = 0; kt < KT; kt++) {
        CP_WAIT2();
        __syncthreads();
        if (kt + STAGES - 1 < KT) issue(kt + STAGES - 1, (kt + STAGES - 1) & (STAGES - 1));
        CP_COMMIT();

        const int buf = kt & (STAGES - 1);
        const uint32_t aBuf = aBase + (uint32_t)(buf * ASTG * 2);
        const uint32_t bBuf = bBase + (uint32_t)(buf * BSTG * 2);
#pragma unroll
        for (int ks = 0; ks < 2; ks++) {
            const uint32_t aK = (uint32_t)(ks * 32);
            const uint32_t bK = transB ? (uint32_t)(ks * 16 * BTW * 2) : (uint32_t)(ks * 32);
            uint32_t af[4][4], bf[4][2];
#pragma unroll
            for (int mt = 0; mt < 4; mt++)
                LDSM_X4(af[mt][0], af[mt][1], af[mt][2], af[mt][3], aBuf + aOff[mt] + aK);
            if (!transB) {
#pragma unroll
                for (int p = 0; p < 2; p++)
                    LDSM_X4(bf[2*p][0], bf[2*p][1], bf[2*p+1][0], bf[2*p+1][1], bBuf + bOff[p] + bK);
            } else {
#pragma unroll
                for (int p = 0; p < 2; p++)
                    LDSM_X4T(bf[2*p][0], bf[2*p][1], bf[2*p+1][0], bf[2*p+1][1], bBuf + bOff[p] + bK);
            }
#pragma unroll
            for (int mt = 0; mt < 4; mt++)
#pragma unroll
                for (int nt = 0; nt < 4; nt++)
                    mma_f16(acc[mt][nt], af[mt], bf[nt]);
        }
    }

    // ---- epilogue ----
    float*  Cf = (float*) Cv + (long)b * sC;
    __half* Ch = (__half*)Cv + (long)b * sC;
#pragma unroll
    for (int mt = 0; mt < 4; mt++) {
        const int r0 = mBlock + mw + mt * 16 + gr;
#pragma unroll
        for (int half_ = 0; half_ < 2; half_++) {
            const int row = r0 + half_ * 8;
            float rm = 1.0f; int mi = 1;
            if (mode == 1 && rowmask) {
                const int useB = (rowmask2 != nullptr) && (row >= Mhalf);
                const int* rmp = useB ? rowmask2 : rowmask;
                const int rr = useB ? row - Mhalf : row;
                rm = rmp[rr] ? 1.0f : 0.0f;
            }
            if (mode == 2) mi = m1p[(long)b * M + row];
#pragma unroll
            for (int nt = 0; nt < 4; nt++) {
                const int c0 = nBlock + nw + nt * 8 + tg * 2;
                float v0 = acc[mt][nt][half_ * 2 + 0];
                float v1 = acc[mt][nt][half_ * 2 + 1];
                if (mode == 1) {
                    v0 += bias[c0];     v1 += bias[c0 + 1];
                    v0 = (v0 >= 0.0f) ? v0 : SLOPE * v0;
                    v1 = (v1 >= 0.0f) ? v1 : SLOPE * v1;
                    v0 *= rm; v1 *= rm;
                } else if (mode == 2) {
                    const int mj0 = m2p[(long)b * N + c0];
                    const int mj1 = m2p[(long)b * N + c0 + 1];
                    v0 += (mi && mj0) ? 0.0f : NEG_INF_F;
                    v1 += (mi && mj1) ? 0.0f : NEG_INF_F;
                }
                if (outHalf) {
                    *(__half2*)&Ch[(long)row * ldC + c0] = __floats2half2_rn(v0, v1);
                } else {
                    float2 o; o.x = v0; o.y = v1;
                    *(float2*)&Cf[(long)row * ldC + c0] = o;
                }
            }
        }
    }
}

// ---------------- f32 -> f16 elementwise ----------------
__global__ __launch_bounds__(256)
void f2h_kernel(const float* __restrict__ src, __half* __restrict__ dst, int n)
{
    int i = (blockIdx.x * 256 + threadIdx.x) * 4;
    if (i < n) {
        float4 v = *(const float4*)(src + i);
        *(__half2*)(dst + i)     = __floats2half2_rn(v.x, v.y);
        *(__half2*)(dst + i + 2) = __floats2half2_rn(v.z, v.w);
    }
}

// ---------------- Row softmax ----------------
__global__ __launch_bounds__(256)
void softmax_row_kernel(const float* __restrict__ S, __half* __restrict__ O,
                        const int* __restrict__ m1, const int* __restrict__ m2)
{
    const int b = blockIdx.y, i = blockIdx.x;
    const float* row = S + ((long)b * Lc + i) * Lc;
    __half* orow     = O + ((long)b * Lc + i) * Lc;
    const int tid = threadIdx.x;

    float v0 = row[tid], v1 = row[tid + 256];
    __shared__ float red[256];

    red[tid] = fmaxf(v0, v1);
    __syncthreads();
    for (int s = 128; s > 0; s >>= 1) {
        if (tid < s) red[tid] = fmaxf(red[tid], red[tid + s]);
        __syncthreads();
    }
    float mx = red[0];
    __syncthreads();

    float e0 = __expf(v0 - mx), e1 = __expf(v1 - mx);
    red[tid] = e0 + e1;
    __syncthreads();
    for (int s = 128; s > 0; s >>= 1) {
        if (tid < s) red[tid] += red[tid + s];
        __syncthreads();
    }
    float inv = 1.0f / red[0];

    int mi = m1[b * Lc + i];
    float f0 = (mi && m2[b * Lc + tid])       ? 1.0f : 0.0f;
    float f1 = (mi && m2[b * Lc + tid + 256]) ? 1.0f : 0.0f;
    orow[tid]       = __float2half_rn(e0 * inv * f0);
    orow[tid + 256] = __float2half_rn(e1 * inv * f1);
}

// -------- Column softmax, writes TRANSPOSED half result --------
__global__ __launch_bounds__(1024)
void softmax_col_kernel(const float* __restrict__ S, __half* __restrict__ OT,
                        const int* __restrict__ m1, const int* __restrict__ m2)
{
    const int b  = blockIdx.y;
    const int tx = threadIdx.x, ty = threadIdx.y;
    const int j  = blockIdx.x * 32 + tx;
    const float* Sb = S  + (long)b * Lc * Lc;
    __half* OTb     = OT + (long)b * Lc * Lc;

    float vals[16];
    float lmax = -1e30f;
#pragma unroll
    for (int it = 0; it < 16; it++) {
        int i = ty + it * 32;
        vals[it] = Sb[(long)i * Lc + j];
        lmax = fmaxf(lmax, vals[it]);
    }
    __shared__ float red[32][33];
    red[ty][tx] = lmax;
    __syncthreads();
    for (int s = 16; s > 0; s >>= 1) {
        if (ty < s) red[ty][tx] = fmaxf(red[ty][tx], red[ty + s][tx]);
        __syncthreads();
    }
    float mx = red[0][tx];
    __syncthreads();

    float lsum = 0.0f;
#pragma unroll
    for (int it = 0; it < 16; it++) {
        vals[it] = __expf(vals[it] - mx);
        lsum += vals[it];
    }
    red[ty][tx] = lsum;
    __syncthreads();
    for (int s = 16; s > 0; s >>= 1) {
        if (ty < s) red[ty][tx] += red[ty + s][tx];
        __syncthreads();
    }
    float inv = 1.0f / red[0][tx];
    __syncthreads();

    const int mj = m2[b * Lc + j];
    const int j0 = blockIdx.x * 32;
#pragma unroll
    for (int it = 0; it < 16; it++) {
        int i = ty + it * 32;
        float f = (mj && m1[b * Lc + i]) ? 1.0f : 0.0f;
        float v = vals[it] * inv * f;
        red[ty][tx] = v;
        __syncthreads();
        OTb[(long)(j0 + ty) * Lc + it * 32 + tx] = __float2half_rn(red[tx][ty]);
        __syncthreads();
    }
}

// ---------------- Launch ----------------
extern "C" void kernel_launch(void* const* d_in, const int* in_sizes, int n_in,
                              void* d_out, int out_size)
{
    const float* r1    = (const float*)d_in[0];
    const float* r2    = (const float*)d_in[1];
    const int*   mask1 = (const int*)  d_in[2];
    const int*   mask2 = (const int*)  d_in[3];
    const float* W1    = (const float*)d_in[4];
    const float* b1    = (const float*)d_in[5];
    const float* W2    = (const float*)d_in[6];
    const float* b2    = (const float*)d_in[7];
    const float* Wc1   = (const float*)d_in[8];
    const float* bc1   = (const float*)d_in[9];
    const float* Wc2   = (const float*)d_in[10];
    const float* bc2   = (const float*)d_in[11];
    float* out = (float*)d_out;

    __half *rh, *hh, *rmh, *oh, *ch, *W1h, *W2h, *Wc1h, *Wc2h;
    float *S;
    cudaGetSymbolAddress((void**)&rh,   g_rh);
    cudaGetSymbolAddress((void**)&hh,   g_hh);
    cudaGetSymbolAddress((void**)&rmh,  g_rmh);
    cudaGetSymbolAddress((void**)&oh,   g_oh);
    cudaGetSymbolAddress((void**)&ch,   g_ch);
    cudaGetSymbolAddress((void**)&W1h,  g_W1h);
    cudaGetSymbolAddress((void**)&W2h,  g_W2h);
    cudaGetSymbolAddress((void**)&Wc1h, g_Wc1h);
    cudaGetSymbolAddress((void**)&Wc2h, g_Wc2h);
    cudaGetSymbolAddress((void**)&S,    g_S);

    cudaFuncSetAttribute(gemm_h, cudaFuncAttributeMaxDynamicSharedMemorySize, GSMEM);

    const long LD = (long)Lc * Dc;   // 262144
    const int  M2 = 2 * Bc * Lc;     // 65536
    dim3 blk(256);
    dim3 gridFused(Dc / BN, M2 / BM, 1);        // (4, 512)
    dim3 gridVal(Dc / BN, Lc / BM, 2 * Bc);     // (4, 4, 128)

    // ---- inputs & weights -> half (no transposes: trans-B path) ----
    f2h_kernel<<<BLD / 4 / 256, 256>>>(r1, rh,       BLD);
    f2h_kernel<<<BLD / 4 / 256, 256>>>(r2, rh + BLD, BLD);
    f2h_kernel<<<Dc*Dc / 4 / 256, 256>>>(W1,  W1h,  Dc*Dc);
    f2h_kernel<<<Dc*Dc / 4 / 256, 256>>>(W2,  W2h,  Dc*Dc);
    f2h_kernel<<<2*Dc*Dc / 4 / 256, 256>>>(Wc1, Wc1h, 2*Dc*Dc);
    f2h_kernel<<<Dc*Dc / 4 / 256, 256>>>(Wc2, Wc2h, Dc*Dc);

    // ---- MLP layer 1 (fused r1|r2; B = W1 [K][N], trans) ----
    gemm_h<<<gridFused, blk, GSMEM>>>(rh, rh, W1h, hh,
        M2, Dc, Dc, 0, Dc, Dc, Dc, Dc, 0, 0, 0, 0,
        b1, nullptr, nullptr, 0, nullptr, nullptr, 1, 1, 1, 0);
    // ---- MLP layer 2 ----
    gemm_h<<<gridFused, blk, GSMEM>>>(hh, hh, W2h, rmh,
        M2, Dc, Dc, 0, Dc, Dc, Dc, Dc, 0, 0, 0, 0,
        b2, mask1, mask2, Bc*Lc, nullptr, nullptr, 1, 1, 1, 0);

    // ---- Scores: S (f32) = r1m @ r2m^T + mask (B = r2m [N][K], normal) ----
    gemm_h<<<dim3(Lc/BN, Lc/BM, Bc), blk, GSMEM>>>(rmh, rmh, rmh + BLD, S,
        Lc, Lc, Dc, 0, Dc, Dc, Dc, Lc, LD, LD, LD, LD,
        nullptr, nullptr, nullptr, 0, mask1, mask2, 2, 0, 0, 0);

    // ---- Softmaxes -> oh = [o1 | o2T] ----
    softmax_col_kernel<<<dim3(Lc/32, Bc), dim3(32, 32)>>>(S, oh + BLD, mask1, mask2);
    softmax_row_kernel<<<dim3(Lc, Bc), 256>>>(S, oh, mask1, mask2);

    // ---- value GEMMs fused (z=128): B = rmh[z^64] [K=L][N=D], trans ----
    gemm_h<<<gridVal, blk, GSMEM>>>(oh, oh, rmh, ch,
        Lc, Dc, Lc, 0, Lc, Lc, Dc, Dc, LD, LD, LD, LD,
        nullptr, nullptr, nullptr, 0, nullptr, nullptr, 0, 1, 1, 64);

    // ---- Compare layer 1 fused: [rm | c] @ Wc1 (K=1024, trans B) ----
    gemm_h<<<gridFused, blk, GSMEM>>>(rmh, ch, Wc1h, hh,
        M2, Dc, 2*Dc, Dc, Dc, Dc, Dc, Dc, 0, 0, 0, 0,
        bc1, nullptr, nullptr, 0, nullptr, nullptr, 1, 1, 1, 0);
    // ---- Compare layer 2 fused -> out (f32) ----
    gemm_h<<<gridFused, blk, GSMEM>>>(hh, hh, Wc2h, out,
        M2, Dc, Dc, 0, Dc, Dc, Dc, Dc, 0, 0, 0, 0,
        bc2, mask1, mask2, Bc*Lc, nullptr, nullptr, 1, 0, 1, 0);
}

// round 16
// speedup vs baseline: 1.1863x; 1.0638x over previous
#include <cuda_runtime.h>
#include <cuda_fp16.h>
#include <cstdint>

// InterAttention (ESIM-style) on GB300 — fp16 mma.sync, cp.async 4-stage,
// ldmatrix(+.trans). R16: gemm_h unchanged from R15 (best); non-GEMM tail
// trimmed — merged f2h launches, warp-per-row softmax, cheaper col-softmax.

#define NEG_INF_F (-1e10f)
#define SLOPE 0.01f
#define Bc 64
#define Lc 512
#define Dc 512
#define BLD (Bc*Lc*Dc)

// ---- scratch ----
__device__ __half g_rh  [2*BLD];   // r1h | r2h
__device__ __half g_hh  [2*BLD];   // hidden
__device__ __half g_rmh [2*BLD];   // r1m | r2m
__device__ __half g_oh  [2*BLD];   // o1  | o2T
__device__ __half g_ch  [2*BLD];   // c1  | c2
__device__ __half g_W1h [Dc*Dc];   // [K][N] as given
__device__ __half g_W2h [Dc*Dc];
__device__ __half g_Wc1h[2*Dc*Dc];
__device__ __half g_Wc2h[Dc*Dc];
__device__ float  g_S[BLD];

__device__ __forceinline__ void mma_f16(float* c, const uint32_t* a, const uint32_t* b) {
    asm volatile(
        "mma.sync.aligned.m16n8k16.row.col.f32.f16.f16.f32 "
        "{%0,%1,%2,%3}, {%4,%5,%6,%7}, {%8,%9}, {%0,%1,%2,%3};"
        : "+f"(c[0]), "+f"(c[1]), "+f"(c[2]), "+f"(c[3])
        : "r"(a[0]), "r"(a[1]), "r"(a[2]), "r"(a[3]), "r"(b[0]), "r"(b[1]));
}
#define LDSM_X4(r0, r1, r2, r3, addr) \
    asm volatile("ldmatrix.sync.aligned.m8n8.x4.shared.b16 {%0,%1,%2,%3}, [%4];" \
        : "=r"(r0), "=r"(r1), "=r"(r2), "=r"(r3) : "r"(addr))
#define LDSM_X4T(r0, r1, r2, r3, addr) \
    asm volatile("ldmatrix.sync.aligned.m8n8.x4.trans.shared.b16 {%0,%1,%2,%3}, [%4];" \
        : "=r"(r0), "=r"(r1), "=r"(r2), "=r"(r3) : "r"(addr))
#define CP_ASYNC16(saddr, gptr) \
    asm volatile("cp.async.cg.shared.global [%0], [%1], 16;" :: "r"(saddr), "l"(gptr) : "memory")
#define CP_COMMIT() asm volatile("cp.async.commit_group;" ::: "memory")
#define CP_WAIT2()  asm volatile("cp.async.wait_group 2;" ::: "memory")

__device__ __forceinline__ uint32_t smem_u32(const void* p){
    uint32_t a;
    asm("{ .reg .u64 t; cvta.to.shared.u64 t, %1; cvt.u32.u64 %0, t; }":"=r"(a):"l"(p));
    return a;
}

// ---------------- fp16 GEMM (identical to R15) ----------------
#define BM 128
#define BN 128
#define BKH 32
#define SWH 40
#define BTW 136
#define STAGES 4
#define ASTG (BM*SWH)
#define BSTG (BM*SWH)
#define GSMEM (STAGES*(ASTG+BSTG)*2)   // 81920 B

__global__ __launch_bounds__(256, 2)
void gemm_h(const __half* __restrict__ A, const __half* __restrict__ A2,
            const __half* __restrict__ B, void* __restrict__ Cv,
            int M, int N, int K, int Ksplit,
            int ldA, int ldA2, int ldB, int ldC,
            long sA, long sA2, long sB, long sC,
            const float* __restrict__ bias,
            const int* __restrict__ rowmask, const int* __restrict__ rowmask2,
            int Mhalf,
            const int* __restrict__ m1p, const int* __restrict__ m2p,
            int mode, int outHalf, int transB, int bXor)
{
    extern __shared__ __half smem[];
    __half* As = smem;
    __half* Bs = smem + STAGES*ASTG;

    const int b = blockIdx.z;
    const __half* Ab  = A  + (long)b * sA;
    const __half* A2b = A2 + (long)b * sA2;
    const __half* Bb  = B  + (long)(b ^ bXor) * sB;

    const int tid = threadIdx.x;
    const int mBlock = blockIdx.y * BM;
    const int nBlock = blockIdx.x * BN;

    const int warp = tid >> 5, lane = tid & 31;
    const int mw = (warp >> 2) * 64;
    const int nw = (warp & 3) * 32;
    const int gr = lane >> 2;
    const int tg = lane & 3;
    const int g  = lane >> 3;

    const uint32_t aBase = smem_u32(As);
    const uint32_t bBase = smem_u32(Bs);
    uint32_t aOff[4], bOff[2];
#pragma unroll
    for (int mt = 0; mt < 4; mt++)
        aOff[mt] = (uint32_t)(((mw + mt * 16 + (lane & 15)) * SWH + (lane >> 4) * 8) * 2);
    if (!transB) {
#pragma unroll
        for (int p = 0; p < 2; p++)
            bOff[p] = (uint32_t)(((nw + (p * 2 + (g >> 1)) * 8 + (lane & 7)) * SWH + (g & 1) * 8) * 2);
    } else {
#pragma unroll
        for (int p = 0; p < 2; p++)
            bOff[p] = (uint32_t)((((g & 1) * 8 + (lane & 7)) * BTW + nw + (p * 2 + (g >> 1)) * 8) * 2);
    }

    float acc[4][4][4];
#pragma unroll
    for (int i = 0; i < 4; i++)
#pragma unroll
        for (int j = 0; j < 4; j++)
#pragma unroll
            for (int q = 0; q < 4; q++) acc[i][j][q] = 0.0f;

    const int KT = K / BKH;

    auto issue = [&](int kt, int stg) {
        const int k0 = kt * BKH;
        const __half* Ap; int kb, ld;
        if (k0 < Ksplit) { Ap = Ab;  kb = k0;          ld = ldA;  }
        else             { Ap = A2b; kb = k0 - Ksplit; ld = ldA2; }
        const uint32_t sa = aBase + (uint32_t)(stg * ASTG * 2);
        const uint32_t sb = bBase + (uint32_t)(stg * BSTG * 2);
        {
            const int r0 = tid >> 2;
            const int c0 = (tid & 2) * 8;
            const int h0 = (tid & 1) * 8;
#pragma unroll
            for (int p = 0; p < 2; p++) {
                const int r = r0 + p * 64;
                CP_ASYNC16(sa + (uint32_t)((r * SWH + c0 + h0) * 2),
                           Ap + (long)(mBlock + r) * ld + kb + c0 + h0);
            }
        }
        if (!transB) {
            const int r0 = tid >> 2;
            const int c0 = (tid & 2) * 8;
            const int h0 = (tid & 1) * 8;
#pragma unroll
            for (int p = 0; p < 2; p++) {
                const int r = r0 + p * 64;
                CP_ASYNC16(sb + (uint32_t)((r * SWH + c0 + h0) * 2),
                           Bb + (long)(nBlock + r) * ldB + k0 + c0 + h0);
            }
        } else {
            const int r = tid >> 3;
            const int c = (tid & 7) * 16;
            const __half* gp = Bb + (long)(k0 + r) * ldB + nBlock + c;
            const uint32_t s = sb + (uint32_t)((r * BTW + c) * 2);
            CP_ASYNC16(s, gp);
            CP_ASYNC16(s + 16, gp + 8);
        }
    };

#pragma unroll
    for (int s = 0; s < STAGES - 1; s++) { issue(s, s); CP_COMMIT(); }

    for (int kt = 0; kt < KT; kt++) {
        CP_WAIT2();
        __syncthreads();
        if (kt + STAGES - 1 < KT) issue(kt + STAGES - 1, (kt + STAGES - 1) & (STAGES - 1));
        CP_COMMIT();

        const int buf = kt & (STAGES - 1);
        const uint32_t aBuf = aBase + (uint32_t)(buf * ASTG * 2);
        const uint32_t bBuf = bBase + (uint32_t)(buf * BSTG * 2);
#pragma unroll
        for (int ks = 0; ks < 2; ks++) {
            const uint32_t aK = (uint32_t)(ks * 32);
            const uint32_t bK = transB ? (uint32_t)(ks * 16 * BTW * 2) : (uint32_t)(ks * 32);
            uint32_t af[4][4], bf[4][2];
#pragma unroll
            for (int mt = 0; mt < 4; mt++)
                LDSM_X4(af[mt][0], af[mt][1], af[mt][2], af[mt][3], aBuf + aOff[mt] + aK);
            if (!transB) {
#pragma unroll
                for (int p = 0; p < 2; p++)
                    LDSM_X4(bf[2*p][0], bf[2*p][1], bf[2*p+1][0], bf[2*p+1][1], bBuf + bOff[p] + bK);
            } else {
#pragma unroll
                for (int p = 0; p < 2; p++)
                    LDSM_X4T(bf[2*p][0], bf[2*p][1], bf[2*p+1][0], bf[2*p+1][1], bBuf + bOff[p] + bK);
            }
#pragma unroll
            for (int mt = 0; mt < 4; mt++)
#pragma unroll
                for (int nt = 0; nt < 4; nt++)
                    mma_f16(acc[mt][nt], af[mt], bf[nt]);
        }
    }

    float*  Cf = (float*) Cv + (long)b * sC;
    __half* Ch = (__half*)Cv + (long)b * sC;
#pragma unroll
    for (int mt = 0; mt < 4; mt++) {
        const int r0 = mBlock + mw + mt * 16 + gr;
#pragma unroll
        for (int half_ = 0; half_ < 2; half_++) {
            const int row = r0 + half_ * 8;
            float rm = 1.0f; int mi = 1;
            if (mode == 1 && rowmask) {
                const int useB = (rowmask2 != nullptr) && (row >= Mhalf);
                const int* rmp = useB ? rowmask2 : rowmask;
                const int rr = useB ? row - Mhalf : row;
                rm = rmp[rr] ? 1.0f : 0.0f;
            }
            if (mode == 2) mi = m1p[(long)b * M + row];
#pragma unroll
            for (int nt = 0; nt < 4; nt++) {
                const int c0 = nBlock + nw + nt * 8 + tg * 2;
                float v0 = acc[mt][nt][half_ * 2 + 0];
                float v1 = acc[mt][nt][half_ * 2 + 1];
                if (mode == 1) {
                    v0 += bias[c0];     v1 += bias[c0 + 1];
                    v0 = (v0 >= 0.0f) ? v0 : SLOPE * v0;
                    v1 = (v1 >= 0.0f) ? v1 : SLOPE * v1;
                    v0 *= rm; v1 *= rm;
                } else if (mode == 2) {
                    const int mj0 = m2p[(long)b * N + c0];
                    const int mj1 = m2p[(long)b * N + c0 + 1];
                    v0 += (mi && mj0) ? 0.0f : NEG_INF_F;
                    v1 += (mi && mj1) ? 0.0f : NEG_INF_F;
                }
                if (outHalf) {
                    *(__half2*)&Ch[(long)row * ldC + c0] = __floats2half2_rn(v0, v1);
                } else {
                    float2 o; o.x = v0; o.y = v1;
                    *(float2*)&Cf[(long)row * ldC + c0] = o;
                }
            }
        }
    }
}

// ---------------- merged f32->f16: inputs (r1|r2 -> rh) ----------------
__global__ __launch_bounds__(256)
void f2h_in(const float* __restrict__ r1, const float* __restrict__ r2,
            __half* __restrict__ dst)
{
    long i = ((long)blockIdx.x * 256 + threadIdx.x) * 4;
    const float* src = (i < BLD) ? (r1 + i) : (r2 + (i - BLD));
    float4 v = *(const float4*)src;
    *(__half2*)(dst + i)     = __floats2half2_rn(v.x, v.y);
    *(__half2*)(dst + i + 2) = __floats2half2_rn(v.z, v.w);
}

// ---------------- merged f32->f16: all 4 weights ----------------
#define WSEG1 (Dc*Dc)          // 262144
#define WSEG2 (2*Dc*Dc)        // 524288
#define WSEG3 (4*Dc*Dc)        // 1048576 (after Wc1's 2*Dc*Dc)
#define WTOT  (5*Dc*Dc)        // 1310720
__global__ __launch_bounds__(256)
void f2h_w(const float* __restrict__ W1, const float* __restrict__ W2,
           const float* __restrict__ Wc1, const float* __restrict__ Wc2,
           __half* __restrict__ W1h, __half* __restrict__ W2h,
           __half* __restrict__ Wc1h, __half* __restrict__ Wc2h)
{
    long i = ((long)blockIdx.x * 256 + threadIdx.x) * 4;
    const float* s; __half* d; long off;
    if (i < WSEG1)      { s = W1;  d = W1h;  off = i; }
    else if (i < WSEG2) { s = W2;  d = W2h;  off = i - WSEG1; }
    else if (i < WSEG3) { s = Wc1; d = Wc1h; off = i - WSEG2; }
    else                { s = Wc2; d = Wc2h; off = i - WSEG3; }
    float4 v = *(const float4*)(s + off);
    *(__half2*)(d + off)     = __floats2half2_rn(v.x, v.y);
    *(__half2*)(d + off + 2) = __floats2half2_rn(v.z, v.w);
}

// ---------------- Row softmax: warp-per-row, shuffle reductions ----------------
__global__ __launch_bounds__(256)
void softmax_row_kernel(const float* __restrict__ S, __half* __restrict__ O,
                        const int* __restrict__ m1, const int* __restrict__ m2)
{
    const int b = blockIdx.y;
    const int i = blockIdx.x * 8 + (threadIdx.x >> 5);
    const int lane = threadIdx.x & 31;
    const float* row = S + ((long)b * Lc + i) * Lc;
    __half* orow     = O + ((long)b * Lc + i) * Lc;

    float v[16];
    float mx = -1e30f;
#pragma unroll
    for (int q = 0; q < 16; q++) {
        v[q] = row[lane + 32 * q];
        mx = fmaxf(mx, v[q]);
    }
#pragma unroll
    for (int o = 16; o > 0; o >>= 1)
        mx = fmaxf(mx, __shfl_xor_sync(0xffffffffu, mx, o));

    float sum = 0.0f;
#pragma unroll
    for (int q = 0; q < 16; q++) { v[q] = __expf(v[q] - mx); sum += v[q]; }
#pragma unroll
    for (int o = 16; o > 0; o >>= 1)
        sum += __shfl_xor_sync(0xffffffffu, sum, o);
    const float inv = 1.0f / sum;

    const int mi = m1[b * Lc + i];
#pragma unroll
    for (int q = 0; q < 16; q++) {
        float f = (mi && m2[b * Lc + lane + 32 * q]) ? 1.0f : 0.0f;
        orow[lane + 32 * q] = __float2half_rn(v[q] * inv * f);
    }
}

// -------- Column softmax, TRANSPOSED half out; 2 tiles per sync round --------
__global__ __launch_bounds__(1024)
void softmax_col_kernel(const float* __restrict__ S, __half* __restrict__ OT,
                        const int* __restrict__ m1, const int* __restrict__ m2)
{
    const int b  = blockIdx.y;
    const int tx = threadIdx.x, ty = threadIdx.y;
    const int j  = blockIdx.x * 32 + tx;
    const float* Sb = S  + (long)b * Lc * Lc;
    __half* OTb     = OT + (long)b * Lc * Lc;

    float vals[16];
    float lmax = -1e30f;
#pragma unroll
    for (int it = 0; it < 16; it++) {
        int i = ty + it * 32;
        vals[it] = Sb[(long)i * Lc + j];
        lmax = fmaxf(lmax, vals[it]);
    }
    __shared__ float red[32][33];
    __shared__ float stg[2][32][33];
    red[ty][tx] = lmax;
    __syncthreads();
    for (int s = 16; s > 0; s >>= 1) {
        if (ty < s) red[ty][tx] = fmaxf(red[ty][tx], red[ty + s][tx]);
        __syncthreads();
    }
    float mx = red[0][tx];
    __syncthreads();

    float lsum = 0.0f;
#pragma unroll
    for (int it = 0; it < 16; it++) {
        vals[it] = __expf(vals[it] - mx);
        lsum += vals[it];
    }
    red[ty][tx] = lsum;
    __syncthreads();
    for (int s = 16; s > 0; s >>= 1) {
        if (ty < s) red[ty][tx] += red[ty + s][tx];
        __syncthreads();
    }
    float inv = 1.0f / red[0][tx];
    __syncthreads();

    const int mj = m2[b * Lc + j];
    const int j0 = blockIdx.x * 32;
#pragma unroll
    for (int it = 0; it < 16; it += 2) {
        int i0 = ty + it * 32;
        int i1 = ty + (it + 1) * 32;
        float f0 = (mj && m1[b * Lc + i0]) ? 1.0f : 0.0f;
        float f1 = (mj && m1[b * Lc + i1]) ? 1.0f : 0.0f;
        stg[0][ty][tx] = vals[it]     * inv * f0;
        stg[1][ty][tx] = vals[it + 1] * inv * f1;
        __syncthreads();
        OTb[(long)(j0 + ty) * Lc + it * 32 + tx]       = __float2half_rn(stg[0][tx][ty]);
        OTb[(long)(j0 + ty) * Lc + (it + 1) * 32 + tx] = __float2half_rn(stg[1][tx][ty]);
        __syncthreads();
    }
}

// ---------------- Launch ----------------
extern "C" void kernel_launch(void* const* d_in, const int* in_sizes, int n_in,
                              void* d_out, int out_size)
{
    const float* r1    = (const float*)d_in[0];
    const float* r2    = (const float*)d_in[1];
    const int*   mask1 = (const int*)  d_in[2];
    const int*   mask2 = (const int*)  d_in[3];
    const float* W1    = (const float*)d_in[4];
    const float* b1    = (const float*)d_in[5];
    const float* W2    = (const float*)d_in[6];
    const float* b2    = (const float*)d_in[7];
    const float* Wc1   = (const float*)d_in[8];
    const float* bc1   = (const float*)d_in[9];
    const float* Wc2   = (const float*)d_in[10];
    const float* bc2   = (const float*)d_in[11];
    float* out = (float*)d_out;

    __half *rh, *hh, *rmh, *oh, *ch, *W1h, *W2h, *Wc1h, *Wc2h;
    float *S;
    cudaGetSymbolAddress((void**)&rh,   g_rh);
    cudaGetSymbolAddress((void**)&hh,   g_hh);
    cudaGetSymbolAddress((void**)&rmh,  g_rmh);
    cudaGetSymbolAddress((void**)&oh,   g_oh);
    cudaGetSymbolAddress((void**)&ch,   g_ch);
    cudaGetSymbolAddress((void**)&W1h,  g_W1h);
    cudaGetSymbolAddress((void**)&W2h,  g_W2h);
    cudaGetSymbolAddress((void**)&Wc1h, g_Wc1h);
    cudaGetSymbolAddress((void**)&Wc2h, g_Wc2h);
    cudaGetSymbolAddress((void**)&S,    g_S);

    cudaFuncSetAttribute(gemm_h, cudaFuncAttributeMaxDynamicSharedMemorySize, GSMEM);

    const long LD = (long)Lc * Dc;   // 262144
    const int  M2 = 2 * Bc * Lc;     // 65536
    dim3 blk(256);
    dim3 gridFused(Dc / BN, M2 / BM, 1);
    dim3 gridVal(Dc / BN, Lc / BM, 2 * Bc);

    // ---- merged conversions (2 launches) ----
    f2h_in<<<2 * BLD / 1024, 256>>>(r1, r2, rh);
    f2h_w<<<WTOT / 1024, 256>>>(W1, W2, Wc1, Wc2, W1h, W2h, Wc1h, Wc2h);

    // ---- MLP layer 1 (fused r1|r2; B = W1 [K][N], trans) ----
    gemm_h<<<gridFused, blk, GSMEM>>>(rh, rh, W1h, hh,
        M2, Dc, Dc, 0, Dc, Dc, Dc, Dc, 0, 0, 0, 0,
        b1, nullptr, nullptr, 0, nullptr, nullptr, 1, 1, 1, 0);
    // ---- MLP layer 2 ----
    gemm_h<<<gridFused, blk, GSMEM>>>(hh, hh, W2h, rmh,
        M2, Dc, Dc, 0, Dc, Dc, Dc, Dc, 0, 0, 0, 0,
        b2, mask1, mask2, Bc*Lc, nullptr, nullptr, 1, 1, 1, 0);

    // ---- Scores: S (f32) = r1m @ r2m^T + mask (B normal) ----
    gemm_h<<<dim3(Lc/BN, Lc/BM, Bc), blk, GSMEM>>>(rmh, rmh, rmh + BLD, S,
        Lc, Lc, Dc, 0, Dc, Dc, Dc, Lc, LD, LD, LD, LD,
        nullptr, nullptr, nullptr, 0, mask1, mask2, 2, 0, 0, 0);

    // ---- Softmaxes -> oh = [o1 | o2T] ----
    softmax_col_kernel<<<dim3(Lc/32, Bc), dim3(32, 32)>>>(S, oh + BLD, mask1, mask2);
    softmax_row_kernel<<<dim3(Lc/8, Bc), 256>>>(S, oh, mask1, mask2);

    // ---- value GEMMs fused (z=128): B = rmh[z^64] [K=L][N=D], trans ----
    gemm_h<<<gridVal, blk, GSMEM>>>(oh, oh, rmh, ch,
        Lc, Dc, Lc, 0, Lc, Lc, Dc, Dc, LD, LD, LD, LD,
        nullptr, nullptr, nullptr, 0, nullptr, nullptr, 0, 1, 1, 64);

    // ---- Compare layer 1 fused: [rm | c] @ Wc1 (K=1024, trans B) ----
    gemm_h<<<gridFused, blk, GSMEM>>>(rmh, ch, Wc1h, hh,
        M2, Dc, 2*Dc, Dc, Dc, Dc, Dc, Dc, 0, 0, 0, 0,
        bc1, nullptr, nullptr, 0, nullptr, nullptr, 1, 1, 1, 0);
    // ---- Compare layer 2 fused -> out (f32) ----
    gemm_h<<<gridFused, blk, GSMEM>>>(hh, hh, Wc2h, out,
        M2, Dc, Dc, 0, Dc, Dc, Dc, Dc, 0, 0, 0, 0,
        bc2, mask1, mask2, Bc*Lc, nullptr, nullptr, 1, 0, 1, 0);
}